// round 13
// baseline (speedup 1.0000x reference)
#include <cuda_runtime.h>
#include <stdint.h>

// GraphRewiring: transitive closure of body-edge adjacency (attr==0),
// emit shortcut edges (closure & ~adj) appended to original edge list.
//
// R13: BFS-critical-path attack. Same algorithm as R12 (closed-form closure
// via F=closure(pivot), B=reach-to-pivot; coalesced row emit), but grid
// reshaped 64x512 -> 32x1024 so the BFS runs on 32 warps (1 frontier word
// each, half the serialized gather waves), 2 syncs/level via
// __syncthreads_or, and barrier arrivals drop 64->32.
//
//   launch 1: init (zero adj/radj, barrier slots; dtype detect)
//   launch 2: fused, GRID=32 x TPB=1024 (1 block/SM, co-resident):
//     P1  scatter adj/radj bitsets, pivot = max body dst              [bar]
//     P2  blocks 0,1: fwd/bwd BFS from pivot -> F, B (32 warps,1 word/warp)
//         blocks 2..: copy original edges to output head              [bar]
//     P3' per-warp closed-form closure + coalesced full-row emit
//
// Closed-form closure (validated R11/R12):
//   closure(row) = adjrow u U_{k in adjrow} closure(k), absorbed by:
//     (a) k in F&B => closure(k) = F        (zero loads; p in F)
//     (b) k in B   => closure(k) >= F u {p} (one ballot, analytic)
//     (c) F already in acc => any k in F absorbed (closure(k) <= F)
//
// Output layout (float32, out_size = 3*(E+N*N)):
//   [0, E)               : edge_index[0] (src) as float
//   [E, E+NN)            : new_src
//   [E+NN, 2E+NN)        : edge_index[1] (dst) as float
//   [2E+NN, 2E+2NN)      : new_dst
//   [2(E+NN), 2(E+NN)+E) : edge_attr copy
//   [2(E+NN)+E, 3(E+NN)) : new_attr (3.0 if shortcut else -1.0)

#define N_NODES 1024
#define NW 32
#define FULLMASK 0xFFFFFFFFu
#define GRID 32
#define TPB 1024
#define NBAR 4

static __device__ uint32_t g_adj[N_NODES * NW];
static __device__ uint32_t g_radj[N_NODES * NW];
static __device__ uint32_t g_F[NW];
static __device__ uint32_t g_B[NW];
static __device__ int g_pivot;
static __device__ int g_i64flag;
static __device__ int g_bar[NBAR];

// ---------------------------------------------------------------------------
__global__ void init_kernel(const int* __restrict__ ei32) {
    int t = blockIdx.x * blockDim.x + threadIdx.x;   // 0..32767
    g_adj[t] = 0u;
    g_radj[t] = 0u;
    if (t < NBAR) g_bar[t] = 0;
    if (t == 0) {
        g_pivot = -1;
        // int64 little-endian with node ids < 1024 => every odd word is 0.
        int allzero = 1;
        for (int k = 0; k < 64; k++)
            if (ei32[2 * k + 1] != 0) { allzero = 0; break; }
        g_i64flag = allzero;
    }
}

// ---------------------------------------------------------------------------
// Pure-poll grid barrier. 32 blocks x 1024 threads at 1 block/SM => all
// co-resident, spin deadlock-free.
__device__ __forceinline__ void grid_sync(int slot) {
    __syncthreads();
    if (threadIdx.x == 0) {
        __threadfence();
        atomicAdd(&g_bar[slot], 1);
        while (*(volatile int*)&g_bar[slot] < GRID) { }
        __threadfence();
    }
    __syncthreads();
}

// ---------------------------------------------------------------------------
__global__ void __launch_bounds__(TPB, 1)
fused_kernel(const int* __restrict__ ei32, const float* __restrict__ attr,
             float* __restrict__ out, int E) {
    __shared__ uint32_t sR[NW];
    __shared__ int s_pivmax;

    const int tid  = blockIdx.x * TPB + threadIdx.x;   // 0..32767
    const int lane = threadIdx.x & 31;
    const int wid  = threadIdx.x >> 5;                 // 0..31
    const int row  = tid >> 5;                         // warp == row, 0..1023
    const int NN   = N_NODES * N_NODES;
    const int i64  = g_i64flag;

    if (threadIdx.x == 0) s_pivmax = -1;
    __syncthreads();

    // ---- P1: scatter adj/radj + pivot (block-local max, 1 atomic/block) ----
    {
        const int stride = GRID * TPB;                 // 32768
        const int nloops = (E + stride - 1) / stride;
        for (int i = 0; i < nloops; i++) {             // warp-uniform count
            int e = tid + i * stride;
            bool v = (e < E);
            int src = 0, dst = 0; float a = 1.0f;
            if (v) {
                if (i64) { src = ei32[2 * e]; dst = ei32[2 * (E + e)]; }
                else     { src = ei32[e];     dst = ei32[E + e]; }
                a = attr[e];
            }
            bool body = v && (a == 0.0f);
            if (body) {
                atomicOr(&g_adj[src * NW + (dst >> 5)], 1u << (dst & 31));
                atomicOr(&g_radj[dst * NW + (src >> 5)], 1u << (src & 31));
            }
            int m = __reduce_max_sync(FULLMASK, body ? dst : -1);
            if (lane == 0 && m >= 0) atomicMax(&s_pivmax, m);
        }
    }
    __syncthreads();
    if (threadIdx.x == 0 && s_pivmax >= 0) atomicMax(&g_pivot, s_pivmax);
    grid_sync(0);

    // ---- P2: blocks 0,1 = BFS (32 warps, 1 word/warp); others copy edges ---
    if (blockIdx.x <= 1) {
        const uint32_t* Adj = (blockIdx.x == 0) ? g_adj : g_radj;
        const int p = *(volatile int*)&g_pivot;
        if (lane == 0) sR[wid] = Adj[p * NW + wid];    // seed = adj row of p
        __syncthreads();

        uint32_t expanded = 0;                          // own word, in register
        #pragma unroll 1
        for (int level = 0; level < N_NODES + 1; level++) {
            uint32_t cur = sR[wid];                     // post-sync, merged
            uint32_t fr = cur & ~expanded;              // warp-uniform
            expanded = cur;
            if (!__syncthreads_or(fr != 0u)) break;     // sync #1 + reduce

            uint32_t accum = 0;                         // lane l = word l
            const uint32_t* pk = &Adj[(wid << 10) + lane];
            uint32_t bits = fr;
            while (bits) {
                int j0 = __ffs(bits) - 1; bits &= bits - 1;
                int j1 = j0, j2 = j0, j3 = j0;
                int j4 = j0, j5 = j0, j6 = j0, j7 = j0;
                if (bits) { j1 = __ffs(bits) - 1; bits &= bits - 1; }
                if (bits) { j2 = __ffs(bits) - 1; bits &= bits - 1; }
                if (bits) { j3 = __ffs(bits) - 1; bits &= bits - 1; }
                if (bits) { j4 = __ffs(bits) - 1; bits &= bits - 1; }
                if (bits) { j5 = __ffs(bits) - 1; bits &= bits - 1; }
                if (bits) { j6 = __ffs(bits) - 1; bits &= bits - 1; }
                if (bits) { j7 = __ffs(bits) - 1; bits &= bits - 1; }
                uint32_t v0 = pk[j0 << 5];
                uint32_t v1 = pk[j1 << 5];
                uint32_t v2 = pk[j2 << 5];
                uint32_t v3 = pk[j3 << 5];
                uint32_t v4 = pk[j4 << 5];
                uint32_t v5 = pk[j5 << 5];
                uint32_t v6 = pk[j6 << 5];
                uint32_t v7 = pk[j7 << 5];
                accum |= (v0 | v1) | (v2 | v3) | (v4 | v5) | (v6 | v7);
            }
            if (accum) atomicOr(&sR[lane], accum);
            __syncthreads();                            // sync #2: publish
        }
        if (threadIdx.x < NW) {
            if (blockIdx.x == 0) g_F[threadIdx.x] = sR[threadIdx.x];
            else                 g_B[threadIdx.x] = sR[threadIdx.x];
        }
    } else {
        // Copy original edges (coalesced), overlapped with BFS.
        int t2 = (blockIdx.x - 2) * TPB + threadIdx.x;
        for (int e = t2; e < E; e += (GRID - 2) * TPB) {
            int src, dst;
            if (i64) { src = ei32[2 * e]; dst = ei32[2 * (E + e)]; }
            else     { src = ei32[e];     dst = ei32[E + e]; }
            out[e] = (float)src;
            out[(E + NN) + e] = (float)dst;
            out[2 * (E + NN) + e] = attr[e];
        }
    }
    grid_sync(1);

    // ---- P3': closed-form closure + COALESCED full-row emit ----------------
    {
        const uint32_t Fl  = __ldcg(&g_F[lane]);       // lane-resident bitsets
        const uint32_t Bl  = __ldcg(&g_B[lane]);
        const uint32_t FBl = Fl & Bl;
        const int p = *(volatile int*)&g_pivot;
        const uint32_t pbit = (lane == (p >> 5)) ? (1u << (p & 31)) : 0u;

        const uint32_t adjrow = g_adj[(row << 5) + lane];
        const int inB = (__shfl_sync(FULLMASK, Bl, row >> 5) >> (row & 31)) & 1;

        uint32_t acc = adjrow;
        bool haveF = false;
        if (inB) { acc |= Fl | pbit; haveF = true; }   // closure(row) >= F u {p}
        uint32_t expanded = 0;

        #pragma unroll 1
        for (int round = 0; round < N_NODES; round++) {
            uint32_t delta = acc & ~expanded;
            if (!__any_sync(FULLMASK, delta != 0u)) break;
            expanded = acc;
            uint32_t add = 0;

            bool hitB = __any_sync(FULLMASK, (delta & Bl) != 0u);
            bool willF = haveF || hitB;
            if (hitB) add |= Fl | pbit;

            uint32_t loadbits = delta & ~FBl;          // F&B: closure=F, no load
            if (willF) loadbits &= ~Fl;                // F absorbed once F in acc

            uint32_t wordmask = __ballot_sync(FULLMASK, loadbits != 0u);
            while (wordmask) {
                int l = __ffs(wordmask) - 1; wordmask &= wordmask - 1;
                uint32_t bits = __shfl_sync(FULLMASK, loadbits, l);
                const uint32_t* pk = &g_adj[(l << 10) + lane];
                while (bits) {
                    int j0 = __ffs(bits) - 1; bits &= bits - 1;
                    int j1 = j0, j2 = j0, j3 = j0;
                    if (bits) { j1 = __ffs(bits) - 1; bits &= bits - 1; }
                    if (bits) { j2 = __ffs(bits) - 1; bits &= bits - 1; }
                    if (bits) { j3 = __ffs(bits) - 1; bits &= bits - 1; }
                    add |= pk[j0 << 5] | pk[j1 << 5] | pk[j2 << 5] | pk[j3 << 5];
                }
            }

            uint32_t na = acc | add;
            haveF = willF;
            if (__all_sync(FULLMASK, na == acc)) break;
            acc = na;
        }

        // sc for lane's word (row*32+lane); row output span is contiguous.
        uint32_t sc = acc & ~adjrow;
        const float fi = (float)row;
        float* so = out + E + (row << 10);                    // new_src row
        float* dd = out + (E + NN) + E + (row << 10);         // new_dst row
        float* ao = out + 2 * (E + NN) + E + (row << 10);     // new_attr row

        if ((E & 3) == 0) {
            // Coalesced: 8 iterations x 3 float4 stores; lane l covers floats
            // f = it*128 + l*4 + {0..3}; word = it*4 + (l>>3); bit = (l&7)*4+q.
            #pragma unroll
            for (int it = 0; it < 8; it++) {
                int w = (it << 2) + (lane >> 3);
                uint32_t nib = (__shfl_sync(FULLMASK, sc, w) >> ((lane & 7) << 2)) & 0xFu;
                int f = (it << 7) + (lane << 2);
                bool b0 = nib & 1u, b1 = (nib >> 1) & 1u;
                bool b2 = (nib >> 2) & 1u, b3 = (nib >> 3) & 1u;
                float4 s4 = make_float4(b0 ? fi : 0.f, b1 ? fi : 0.f,
                                        b2 ? fi : 0.f, b3 ? fi : 0.f);
                float4 d4 = make_float4(b0 ? (float)(f + 0) : 0.f,
                                        b1 ? (float)(f + 1) : 0.f,
                                        b2 ? (float)(f + 2) : 0.f,
                                        b3 ? (float)(f + 3) : 0.f);
                float4 a4 = make_float4(b0 ? 3.f : -1.f, b1 ? 3.f : -1.f,
                                        b2 ? 3.f : -1.f, b3 ? 3.f : -1.f);
                *(float4*)(so + f) = s4;
                *(float4*)(dd + f) = d4;
                *(float4*)(ao + f) = a4;
            }
        } else {
            // Scalar fallback (unaligned E). Still coalesced per instruction.
            #pragma unroll 1
            for (int it = 0; it < 32; it++) {
                int f = (it << 5) + lane;               // float index in row
                uint32_t scw = __shfl_sync(FULLMASK, sc, f >> 5);
                bool b = (scw >> (f & 31)) & 1u;
                so[f] = b ? fi : 0.f;
                dd[f] = b ? (float)f : 0.f;
                ao[f] = b ? 3.f : -1.f;
            }
        }
    }
}

// ---------------------------------------------------------------------------
extern "C" void kernel_launch(void* const* d_in, const int* in_sizes, int n_in,
                              void* d_out, int out_size) {
    const int* ei = (const int*)d_in[0];
    const float* attr = (const float*)d_in[1];
    float* out = (float*)d_out;
    int E = in_sizes[1];

    init_kernel<<<32, 1024>>>(ei);
    fused_kernel<<<GRID, TPB>>>(ei, attr, out, E);
}

// round 14
// speedup vs baseline: 1.0127x; 1.0127x over previous
#include <cuda_runtime.h>
#include <stdint.h>

// GraphRewiring: transitive closure of body-edge adjacency (attr==0),
// emit shortcut edges (closure & ~adj) appended to original edge list.
//
// R14 = R12 (measured-best skeleton: 64x512, closed-form closure, coalesced
// row emit) + three same-address/sync fixes:
//   1. P3' warm-start data (F, B, pivot) loaded ONCE per block into smem
//      (64 L2 requests grid-wide instead of ~3000 same-sector __ldcg/volatile)
//   2. pivot aggregated in block smem, 1 global atomicMax per block
//   3. the second full grid barrier replaced by a 2-producer FLAG wait
//      (P3' only depends on blocks 0,1 having published F/B)
//
//   launch 1: init (zero adj/radj, barrier slot, flag; dtype detect)
//   launch 2: fused, GRID=64 x TPB=512 (1 block/SM, co-resident):
//     P1  scatter adj/radj bitsets, pivot = max body dst              [bar0]
//     P2  blocks 0,1: fwd/bwd BFS from pivot -> F, B; publish flag
//         blocks 2..: copy original edges to output head         [flag wait]
//     P3' per-warp closed-form closure + coalesced full-row emit
//
// Closed-form closure (validated R11/R12):
//   closure(row) = adjrow u U_{k in adjrow} closure(k), absorbed by:
//     (a) k in F&B => closure(k) = F        (zero loads; p in F)
//     (b) k in B   => closure(k) >= F u {p} (one ballot, analytic)
//     (c) F already in acc => any k in F absorbed (closure(k) <= F)
//
// Output layout (float32, out_size = 3*(E+N*N)):
//   [0, E)               : edge_index[0] (src) as float
//   [E, E+NN)            : new_src
//   [E+NN, 2E+NN)        : edge_index[1] (dst) as float
//   [2E+NN, 2E+2NN)      : new_dst
//   [2(E+NN), 2(E+NN)+E) : edge_attr copy
//   [2(E+NN)+E, 3(E+NN)) : new_attr (3.0 if shortcut else -1.0)

#define N_NODES 1024
#define NW 32
#define FULLMASK 0xFFFFFFFFu
#define GRID 64
#define TPB 512
#define NBAR 2

static __device__ uint32_t g_adj[N_NODES * NW];
static __device__ uint32_t g_radj[N_NODES * NW];
static __device__ uint32_t g_F[NW];
static __device__ uint32_t g_B[NW];
static __device__ int g_pivot;
static __device__ int g_i64flag;
static __device__ int g_bar[NBAR];
static __device__ int g_fbflag;          // F/B published count (0..2)

// ---------------------------------------------------------------------------
__global__ void init_kernel(const int* __restrict__ ei32) {
    int t = blockIdx.x * blockDim.x + threadIdx.x;   // 0..32767
    g_adj[t] = 0u;
    g_radj[t] = 0u;
    if (t < NBAR) g_bar[t] = 0;
    if (t == 0) {
        g_pivot = -1;
        g_fbflag = 0;
        // int64 little-endian with node ids < 1024 => every odd word is 0.
        int allzero = 1;
        for (int k = 0; k < 64; k++)
            if (ei32[2 * k + 1] != 0) { allzero = 0; break; }
        g_i64flag = allzero;
    }
}

// ---------------------------------------------------------------------------
// Pure-poll grid barrier. 64 blocks x 512 threads at 1 block/SM => all
// co-resident, spin deadlock-free.
__device__ __forceinline__ void grid_sync(int slot) {
    __syncthreads();
    if (threadIdx.x == 0) {
        __threadfence();
        atomicAdd(&g_bar[slot], 1);
        while (*(volatile int*)&g_bar[slot] < GRID) { }
        __threadfence();
    }
    __syncthreads();
}

// ---------------------------------------------------------------------------
__global__ void __launch_bounds__(TPB, 1)
fused_kernel(const int* __restrict__ ei32, const float* __restrict__ attr,
             float* __restrict__ out, int E) {
    __shared__ uint32_t sR[NW], sExp[NW], sFr[NW];
    __shared__ uint32_t sF[NW], sB[NW];
    __shared__ int sAny, sPivMax, sPiv;

    const int tid  = blockIdx.x * TPB + threadIdx.x;   // 0..32767
    const int lane = threadIdx.x & 31;
    const int wid  = threadIdx.x >> 5;                 // 0..15
    const int row  = tid >> 5;                         // warp == row, 0..1023
    const int NN   = N_NODES * N_NODES;
    const int i64  = g_i64flag;

    if (threadIdx.x == 0) sPivMax = -1;
    __syncthreads();

    // ---- P1: scatter adj/radj + pivot (smem max, 1 global atomic/block) ----
    {
        const int stride = GRID * TPB;                 // 32768
        const int nloops = (E + stride - 1) / stride;
        for (int i = 0; i < nloops; i++) {             // warp-uniform count
            int e = tid + i * stride;
            bool v = (e < E);
            int src = 0, dst = 0; float a = 1.0f;
            if (v) {
                if (i64) { src = ei32[2 * e]; dst = ei32[2 * (E + e)]; }
                else     { src = ei32[e];     dst = ei32[E + e]; }
                a = attr[e];
            }
            bool body = v && (a == 0.0f);
            if (body) {
                atomicOr(&g_adj[src * NW + (dst >> 5)], 1u << (dst & 31));
                atomicOr(&g_radj[dst * NW + (src >> 5)], 1u << (src & 31));
            }
            int m = __reduce_max_sync(FULLMASK, body ? dst : -1);
            if (lane == 0 && m >= 0) atomicMax(&sPivMax, m);
        }
    }
    __syncthreads();
    if (threadIdx.x == 0 && sPivMax >= 0) atomicMax(&g_pivot, sPivMax);
    grid_sync(0);

    // ---- P2: blocks 0,1 = BFS -> publish flag; blocks 2.. = copy edges -----
    if (blockIdx.x <= 1) {
        const uint32_t* Adj = (blockIdx.x == 0) ? g_adj : g_radj;
        const int p = *(volatile int*)&g_pivot;
        if (threadIdx.x < NW) {
            sR[threadIdx.x] = (p >= 0) ? Adj[p * NW + threadIdx.x] : 0u;
            sExp[threadIdx.x] = 0u;
        }
        __syncthreads();
        if (p >= 0) {
            for (int level = 0; level < N_NODES + 1; level++) {
                if (threadIdx.x == 0) sAny = 0;
                __syncthreads();
                if (threadIdx.x < NW) {
                    sFr[threadIdx.x] = sR[threadIdx.x] & ~sExp[threadIdx.x];
                    sExp[threadIdx.x] = sR[threadIdx.x];
                    if (sFr[threadIdx.x]) sAny = 1;    // benign race
                }
                __syncthreads();
                if (!sAny) break;
                uint32_t accum = 0;
                #pragma unroll 1
                for (int ww = wid; ww < NW; ww += 16) { // 16 warps, 2 words ea.
                    uint32_t bits = sFr[ww];            // warp-uniform
                    const uint32_t* pk = &Adj[(ww << 10) + lane];
                    while (bits) {
                        int j0 = __ffs(bits) - 1; bits &= bits - 1;
                        int j1 = j0, j2 = j0, j3 = j0;
                        int j4 = j0, j5 = j0, j6 = j0, j7 = j0;
                        if (bits) { j1 = __ffs(bits) - 1; bits &= bits - 1; }
                        if (bits) { j2 = __ffs(bits) - 1; bits &= bits - 1; }
                        if (bits) { j3 = __ffs(bits) - 1; bits &= bits - 1; }
                        if (bits) { j4 = __ffs(bits) - 1; bits &= bits - 1; }
                        if (bits) { j5 = __ffs(bits) - 1; bits &= bits - 1; }
                        if (bits) { j6 = __ffs(bits) - 1; bits &= bits - 1; }
                        if (bits) { j7 = __ffs(bits) - 1; bits &= bits - 1; }
                        uint32_t v0 = pk[j0 << 5];
                        uint32_t v1 = pk[j1 << 5];
                        uint32_t v2 = pk[j2 << 5];
                        uint32_t v3 = pk[j3 << 5];
                        uint32_t v4 = pk[j4 << 5];
                        uint32_t v5 = pk[j5 << 5];
                        uint32_t v6 = pk[j6 << 5];
                        uint32_t v7 = pk[j7 << 5];
                        accum |= (v0 | v1) | (v2 | v3) | (v4 | v5) | (v6 | v7);
                    }
                }
                if (accum) atomicOr(&sR[lane], accum);
                __syncthreads();
            }
        }
        if (threadIdx.x < NW) {
            if (blockIdx.x == 0) g_F[threadIdx.x] = sR[threadIdx.x];
            else                 g_B[threadIdx.x] = sR[threadIdx.x];
        }
        __syncthreads();
        if (threadIdx.x == 0) {
            __threadfence();                 // publish F (or B) before flag
            atomicAdd(&g_fbflag, 1);
        }
    } else {
        // Copy original edges (coalesced), overlapped with BFS.
        int t2 = (blockIdx.x - 2) * TPB + threadIdx.x;  // 0..31743
        for (int e = t2; e < E; e += (GRID - 2) * TPB) {
            int src, dst;
            if (i64) { src = ei32[2 * e]; dst = ei32[2 * (E + e)]; }
            else     { src = ei32[e];     dst = ei32[E + e]; }
            out[e] = (float)src;
            out[(E + NN) + e] = (float)dst;
            out[2 * (E + NN) + e] = attr[e];
        }
    }

    // ---- flag wait: F and B published (2 producers), then smem broadcast ---
    if (threadIdx.x == 0) {
        while (*(volatile int*)&g_fbflag < 2) { }
        __threadfence();                     // acquire
    }
    __syncthreads();
    if (threadIdx.x < NW)            sF[threadIdx.x] = __ldcg(&g_F[threadIdx.x]);
    else if (threadIdx.x < 2 * NW)   sB[threadIdx.x - NW] = __ldcg(&g_B[threadIdx.x - NW]);
    else if (threadIdx.x == 2 * NW)  sPiv = *(volatile int*)&g_pivot;
    __syncthreads();

    // ---- P3': closed-form closure + COALESCED full-row emit ----------------
    {
        const uint32_t Fl  = sF[lane];       // smem broadcast, conflict-free
        const uint32_t Bl  = sB[lane];
        const uint32_t FBl = Fl & Bl;
        const int p = sPiv;
        const uint32_t pbit = (p >= 0 && lane == (p >> 5)) ? (1u << (p & 31)) : 0u;

        const uint32_t adjrow = g_adj[(row << 5) + lane];
        const int inB = (__shfl_sync(FULLMASK, Bl, row >> 5) >> (row & 31)) & 1;

        uint32_t acc = adjrow;
        bool haveF = false;
        if (inB) { acc |= Fl | pbit; haveF = true; }   // closure(row) >= F u {p}
        uint32_t expanded = 0;

        #pragma unroll 1
        for (int round = 0; round < N_NODES; round++) {
            uint32_t delta = acc & ~expanded;
            if (!__any_sync(FULLMASK, delta != 0u)) break;
            expanded = acc;
            uint32_t add = 0;

            bool hitB = __any_sync(FULLMASK, (delta & Bl) != 0u);
            bool willF = haveF || hitB;
            if (hitB) add |= Fl | pbit;

            uint32_t loadbits = delta & ~FBl;          // F&B: closure=F, no load
            if (willF) loadbits &= ~Fl;                // F absorbed once F in acc

            uint32_t wordmask = __ballot_sync(FULLMASK, loadbits != 0u);
            while (wordmask) {
                int l = __ffs(wordmask) - 1; wordmask &= wordmask - 1;
                uint32_t bits = __shfl_sync(FULLMASK, loadbits, l);
                const uint32_t* pk = &g_adj[(l << 10) + lane];
                while (bits) {
                    int j0 = __ffs(bits) - 1; bits &= bits - 1;
                    int j1 = j0, j2 = j0, j3 = j0;
                    if (bits) { j1 = __ffs(bits) - 1; bits &= bits - 1; }
                    if (bits) { j2 = __ffs(bits) - 1; bits &= bits - 1; }
                    if (bits) { j3 = __ffs(bits) - 1; bits &= bits - 1; }
                    add |= pk[j0 << 5] | pk[j1 << 5] | pk[j2 << 5] | pk[j3 << 5];
                }
            }

            uint32_t na = acc | add;
            haveF = willF;
            if (__all_sync(FULLMASK, na == acc)) break;
            acc = na;
        }

        // sc for lane's word (row*32+lane); row output span is contiguous.
        uint32_t sc = acc & ~adjrow;
        const float fi = (float)row;
        float* so = out + E + (row << 10);                    // new_src row
        float* dd = out + (E + NN) + E + (row << 10);         // new_dst row
        float* ao = out + 2 * (E + NN) + E + (row << 10);     // new_attr row

        if ((E & 3) == 0) {
            // Coalesced: 8 iterations x 3 float4 stores; lane l covers floats
            // f = it*128 + l*4 + {0..3}; word = it*4 + (l>>3); bit = (l&7)*4+q.
            #pragma unroll
            for (int it = 0; it < 8; it++) {
                int w = (it << 2) + (lane >> 3);
                uint32_t nib = (__shfl_sync(FULLMASK, sc, w) >> ((lane & 7) << 2)) & 0xFu;
                int f = (it << 7) + (lane << 2);
                bool b0 = nib & 1u, b1 = (nib >> 1) & 1u;
                bool b2 = (nib >> 2) & 1u, b3 = (nib >> 3) & 1u;
                float4 s4 = make_float4(b0 ? fi : 0.f, b1 ? fi : 0.f,
                                        b2 ? fi : 0.f, b3 ? fi : 0.f);
                float4 d4 = make_float4(b0 ? (float)(f + 0) : 0.f,
                                        b1 ? (float)(f + 1) : 0.f,
                                        b2 ? (float)(f + 2) : 0.f,
                                        b3 ? (float)(f + 3) : 0.f);
                float4 a4 = make_float4(b0 ? 3.f : -1.f, b1 ? 3.f : -1.f,
                                        b2 ? 3.f : -1.f, b3 ? 3.f : -1.f);
                *(float4*)(so + f) = s4;
                *(float4*)(dd + f) = d4;
                *(float4*)(ao + f) = a4;
            }
        } else {
            // Scalar fallback (unaligned E). Still coalesced per instruction.
            #pragma unroll 1
            for (int it = 0; it < 32; it++) {
                int f = (it << 5) + lane;               // float index in row
                uint32_t scw = __shfl_sync(FULLMASK, sc, f >> 5);
                bool b = (scw >> (f & 31)) & 1u;
                so[f] = b ? fi : 0.f;
                dd[f] = b ? (float)f : 0.f;
                ao[f] = b ? 3.f : -1.f;
            }
        }
    }
}

// ---------------------------------------------------------------------------
extern "C" void kernel_launch(void* const* d_in, const int* in_sizes, int n_in,
                              void* d_out, int out_size) {
    const int* ei = (const int*)d_in[0];
    const float* attr = (const float*)d_in[1];
    float* out = (float*)d_out;
    int E = in_sizes[1];

    init_kernel<<<64, 512>>>(ei);
    fused_kernel<<<GRID, TPB>>>(ei, attr, out, E);
}

// round 15
// speedup vs baseline: 1.2124x; 1.1973x over previous
#include <cuda_runtime.h>
#include <stdint.h>

// GraphRewiring: transitive closure of body-edge adjacency (attr==0),
// emit shortcut edges (closure & ~adj) appended to original edge list.
//
// R15: CLEAN 4-LAUNCH SPLIT — no software barriers, no spins, no flags,
// no co-residency constraints. CUDA-graph edges provide all ordering.
// Rationale: the fused/persistent construction has sat at ~23.5us across
// four structural variants while its phase-sum models ~10-12us; splitting
// removes the persistent machinery AND gives per-phase ncu attribution.
//
//   K1 init : zero adj/radj, pivot=-1; detect int64-vs-int32
//   K2 build: scatter adj/radj bitsets, pivot=max body dst,
//             copy original edges to output head (1 edge per thread)
//   K3 bfs  : 2 blocks x 1024 (block0 fwd, block1 bwd), 32 warps,
//             1 frontier word per warp -> F = closure(pivot), B = reach(pivot)
//   K4 close: per-warp closed-form closure + coalesced full-row emit
//
// Closed-form closure (validated R11/R12):
//   closure(row) = adjrow u U_{k in adjrow} closure(k), absorbed by:
//     (a) k in F&B => closure(k) = F        (zero loads; p in F)
//     (b) k in B   => closure(k) >= F u {p} (one ballot, analytic)
//     (c) F already in acc => any k in F absorbed (closure(k) <= F)
//
// Output layout (float32, out_size = 3*(E+N*N)):
//   [0, E)               : edge_index[0] (src) as float
//   [E, E+NN)            : new_src
//   [E+NN, 2E+NN)        : edge_index[1] (dst) as float
//   [2E+NN, 2E+2NN)      : new_dst
//   [2(E+NN), 2(E+NN)+E) : edge_attr copy
//   [2(E+NN)+E, 3(E+NN)) : new_attr (3.0 if shortcut else -1.0)

#define N_NODES 1024
#define NW 32
#define FULLMASK 0xFFFFFFFFu

static __device__ uint32_t g_adj[N_NODES * NW];
static __device__ uint32_t g_radj[N_NODES * NW];
static __device__ uint32_t g_F[NW];
static __device__ uint32_t g_B[NW];
static __device__ int g_pivot;
static __device__ int g_i64flag;

// ---------------------------------------------------------------------------
// K1: zero scratch, detect dtype.
__global__ void init_kernel(const int* __restrict__ ei32) {
    int t = blockIdx.x * blockDim.x + threadIdx.x;   // 0..32767
    g_adj[t] = 0u;
    g_radj[t] = 0u;
    if (t == 0) {
        g_pivot = -1;
        // int64 little-endian with node ids < 1024 => every odd word is 0.
        int allzero = 1;
        for (int k = 0; k < 64; k++)
            if (ei32[2 * k + 1] != 0) { allzero = 0; break; }
        g_i64flag = allzero;
    }
}

// ---------------------------------------------------------------------------
// K2: scatter adj/radj + pivot + copy originals. One edge per thread.
__global__ void build_kernel(const int* __restrict__ ei32,
                             const float* __restrict__ attr,
                             float* __restrict__ out, int E) {
    __shared__ int sPivMax;
    const int NN = N_NODES * N_NODES;
    if (threadIdx.x == 0) sPivMax = -1;
    __syncthreads();

    int e = blockIdx.x * blockDim.x + threadIdx.x;
    int lane = threadIdx.x & 31;
    bool v = (e < E);
    int src = 0, dst = 0; float a = 1.0f;
    if (v) {
        if (g_i64flag) { src = ei32[2 * e]; dst = ei32[2 * (E + e)]; }
        else           { src = ei32[e];     dst = ei32[E + e]; }
        a = attr[e];
        out[e] = (float)src;
        out[(E + NN) + e] = (float)dst;
        out[2 * (E + NN) + e] = a;
    }
    bool body = v && (a == 0.0f);
    if (body) {
        atomicOr(&g_adj[src * NW + (dst >> 5)], 1u << (dst & 31));
        atomicOr(&g_radj[dst * NW + (src >> 5)], 1u << (src & 31));
    }
    int m = __reduce_max_sync(FULLMASK, body ? dst : -1);
    if (lane == 0 && m >= 0) atomicMax(&sPivMax, m);
    __syncthreads();
    if (threadIdx.x == 0 && sPivMax >= 0) atomicMax(&g_pivot, sPivMax);
}

// ---------------------------------------------------------------------------
// K3: single-source BFS to fixpoint. block 0: forward -> g_F;
//     block 1: backward -> g_B. 32 warps, 1 frontier word per warp.
__global__ void __launch_bounds__(1024) bfs_kernel() {
    __shared__ uint32_t sR[NW];
    const int lane = threadIdx.x & 31;
    const int wid  = threadIdx.x >> 5;               // 0..31

    const uint32_t* Adj = (blockIdx.x == 0) ? g_adj : g_radj;
    const int p = g_pivot;
    if (lane == 0) sR[wid] = (p >= 0) ? Adj[p * NW + wid] : 0u;
    __syncthreads();

    if (p >= 0) {
        uint32_t expanded = 0;                       // own word, in register
        #pragma unroll 1
        for (int level = 0; level < N_NODES + 1; level++) {
            uint32_t cur = sR[wid];                  // post-sync, merged
            uint32_t fr = cur & ~expanded;           // warp-uniform
            expanded = cur;
            if (!__syncthreads_or(fr != 0u)) break;

            uint32_t accum = 0;                      // lane l = word l
            const uint32_t* pk = &Adj[(wid << 10) + lane];
            uint32_t bits = fr;
            while (bits) {
                int j0 = __ffs(bits) - 1; bits &= bits - 1;
                int j1 = j0, j2 = j0, j3 = j0;
                int j4 = j0, j5 = j0, j6 = j0, j7 = j0;
                if (bits) { j1 = __ffs(bits) - 1; bits &= bits - 1; }
                if (bits) { j2 = __ffs(bits) - 1; bits &= bits - 1; }
                if (bits) { j3 = __ffs(bits) - 1; bits &= bits - 1; }
                if (bits) { j4 = __ffs(bits) - 1; bits &= bits - 1; }
                if (bits) { j5 = __ffs(bits) - 1; bits &= bits - 1; }
                if (bits) { j6 = __ffs(bits) - 1; bits &= bits - 1; }
                if (bits) { j7 = __ffs(bits) - 1; bits &= bits - 1; }
                uint32_t v0 = pk[j0 << 5];
                uint32_t v1 = pk[j1 << 5];
                uint32_t v2 = pk[j2 << 5];
                uint32_t v3 = pk[j3 << 5];
                uint32_t v4 = pk[j4 << 5];
                uint32_t v5 = pk[j5 << 5];
                uint32_t v6 = pk[j6 << 5];
                uint32_t v7 = pk[j7 << 5];
                accum |= (v0 | v1) | (v2 | v3) | (v4 | v5) | (v6 | v7);
            }
            if (accum) atomicOr(&sR[lane], accum);
            __syncthreads();
        }
    }
    if (threadIdx.x < NW) {
        if (blockIdx.x == 0) g_F[threadIdx.x] = sR[threadIdx.x];
        else                 g_B[threadIdx.x] = sR[threadIdx.x];
    }
}

// ---------------------------------------------------------------------------
// K4: per-warp closed-form closure + coalesced full-row emit.
// 64 blocks x 512 threads = 1024 warps, warp == row.
__global__ void __launch_bounds__(512)
closure_emit_kernel(float* __restrict__ out, int E) {
    __shared__ uint32_t sF[NW], sB[NW];
    __shared__ int sPiv;

    const int tid  = blockIdx.x * 512 + threadIdx.x;
    const int lane = threadIdx.x & 31;
    const int row  = tid >> 5;                       // 0..1023
    const int NN   = N_NODES * N_NODES;

    if (threadIdx.x < NW)            sF[threadIdx.x] = g_F[threadIdx.x];
    else if (threadIdx.x < 2 * NW)   sB[threadIdx.x - NW] = g_B[threadIdx.x - NW];
    else if (threadIdx.x == 2 * NW)  sPiv = g_pivot;
    __syncthreads();

    const uint32_t Fl  = sF[lane];                   // conflict-free broadcast
    const uint32_t Bl  = sB[lane];
    const uint32_t FBl = Fl & Bl;
    const int p = sPiv;
    const uint32_t pbit = (p >= 0 && lane == (p >> 5)) ? (1u << (p & 31)) : 0u;

    const uint32_t adjrow = g_adj[(row << 5) + lane];
    const int inB = (__shfl_sync(FULLMASK, Bl, row >> 5) >> (row & 31)) & 1;

    uint32_t acc = adjrow;
    bool haveF = false;
    if (inB) { acc |= Fl | pbit; haveF = true; }     // closure(row) >= F u {p}
    uint32_t expanded = 0;

    #pragma unroll 1
    for (int round = 0; round < N_NODES; round++) {
        uint32_t delta = acc & ~expanded;
        if (!__any_sync(FULLMASK, delta != 0u)) break;
        expanded = acc;
        uint32_t add = 0;

        bool hitB = __any_sync(FULLMASK, (delta & Bl) != 0u);
        bool willF = haveF || hitB;
        if (hitB) add |= Fl | pbit;

        uint32_t loadbits = delta & ~FBl;            // F&B: closure=F, no load
        if (willF) loadbits &= ~Fl;                  // F absorbed once in acc

        uint32_t wordmask = __ballot_sync(FULLMASK, loadbits != 0u);
        while (wordmask) {
            int l = __ffs(wordmask) - 1; wordmask &= wordmask - 1;
            uint32_t bits = __shfl_sync(FULLMASK, loadbits, l);
            const uint32_t* pk = &g_adj[(l << 10) + lane];
            while (bits) {
                int j0 = __ffs(bits) - 1; bits &= bits - 1;
                int j1 = j0, j2 = j0, j3 = j0;
                if (bits) { j1 = __ffs(bits) - 1; bits &= bits - 1; }
                if (bits) { j2 = __ffs(bits) - 1; bits &= bits - 1; }
                if (bits) { j3 = __ffs(bits) - 1; bits &= bits - 1; }
                add |= pk[j0 << 5] | pk[j1 << 5] | pk[j2 << 5] | pk[j3 << 5];
            }
        }

        uint32_t na = acc | add;
        haveF = willF;
        if (__all_sync(FULLMASK, na == acc)) break;
        acc = na;
    }

    // sc for lane's word (row*32+lane); row output span is contiguous.
    uint32_t sc = acc & ~adjrow;
    const float fi = (float)row;
    float* so = out + E + (row << 10);                    // new_src row
    float* dd = out + (E + NN) + E + (row << 10);         // new_dst row
    float* ao = out + 2 * (E + NN) + E + (row << 10);     // new_attr row

    if ((E & 3) == 0) {
        // Coalesced: 8 iterations x 3 float4 stores; lane l covers floats
        // f = it*128 + l*4 + {0..3}; word = it*4 + (l>>3); bit = (l&7)*4+q.
        #pragma unroll
        for (int it = 0; it < 8; it++) {
            int w = (it << 2) + (lane >> 3);
            uint32_t nib = (__shfl_sync(FULLMASK, sc, w) >> ((lane & 7) << 2)) & 0xFu;
            int f = (it << 7) + (lane << 2);
            bool b0 = nib & 1u, b1 = (nib >> 1) & 1u;
            bool b2 = (nib >> 2) & 1u, b3 = (nib >> 3) & 1u;
            float4 s4 = make_float4(b0 ? fi : 0.f, b1 ? fi : 0.f,
                                    b2 ? fi : 0.f, b3 ? fi : 0.f);
            float4 d4 = make_float4(b0 ? (float)(f + 0) : 0.f,
                                    b1 ? (float)(f + 1) : 0.f,
                                    b2 ? (float)(f + 2) : 0.f,
                                    b3 ? (float)(f + 3) : 0.f);
            float4 a4 = make_float4(b0 ? 3.f : -1.f, b1 ? 3.f : -1.f,
                                    b2 ? 3.f : -1.f, b3 ? 3.f : -1.f);
            *(float4*)(so + f) = s4;
            *(float4*)(dd + f) = d4;
            *(float4*)(ao + f) = a4;
        }
    } else {
        // Scalar fallback (unaligned E). Still coalesced per instruction.
        #pragma unroll 1
        for (int it = 0; it < 32; it++) {
            int f = (it << 5) + lane;                // float index in row
            uint32_t scw = __shfl_sync(FULLMASK, sc, f >> 5);
            bool b = (scw >> (f & 31)) & 1u;
            so[f] = b ? fi : 0.f;
            dd[f] = b ? (float)f : 0.f;
            ao[f] = b ? 3.f : -1.f;
        }
    }
}

// ---------------------------------------------------------------------------
extern "C" void kernel_launch(void* const* d_in, const int* in_sizes, int n_in,
                              void* d_out, int out_size) {
    const int* ei = (const int*)d_in[0];
    const float* attr = (const float*)d_in[1];
    float* out = (float*)d_out;
    int E = in_sizes[1];

    init_kernel<<<64, 512>>>(ei);
    build_kernel<<<(E + 511) / 512, 512>>>(ei, attr, out, E);
    bfs_kernel<<<2, 1024>>>();
    closure_emit_kernel<<<64, 512>>>(out, E);
}

// round 16
// speedup vs baseline: 1.3542x; 1.1169x over previous
#include <cuda_runtime.h>
#include <stdint.h>

// GraphRewiring: transitive closure of body-edge adjacency (attr==0),
// emit shortcut edges (closure & ~adj) appended to original edge list.
//
// R16 = R15 (clean 4-launch split, measured best) with the issue-bound
// kernels spread across 2x the SMs:
//   - closure_emit: 64x512 -> 128x256 (same 1024 warps, half the per-SM
//     STG.128 issue + L2 write-queue depth)
//   - build/init: 128x256 for the same reason
//
//   K1 init : zero adj/radj, pivot=-1; detect int64-vs-int32
//   K2 build: scatter adj/radj bitsets, pivot=max body dst,
//             copy original edges to output head (1 edge per thread)
//   K3 bfs  : 2 blocks x 1024 (block0 fwd, block1 bwd), 32 warps,
//             1 frontier word per warp -> F = closure(pivot), B = reach(pivot)
//   K4 close: per-warp closed-form closure + coalesced full-row emit
//
// Closed-form closure (validated R11/R12):
//   closure(row) = adjrow u U_{k in adjrow} closure(k), absorbed by:
//     (a) k in F&B => closure(k) = F        (zero loads; p in F)
//     (b) k in B   => closure(k) >= F u {p} (one ballot, analytic)
//     (c) F already in acc => any k in F absorbed (closure(k) <= F)
//
// Output layout (float32, out_size = 3*(E+N*N)):
//   [0, E)               : edge_index[0] (src) as float
//   [E, E+NN)            : new_src
//   [E+NN, 2E+NN)        : edge_index[1] (dst) as float
//   [2E+NN, 2E+2NN)      : new_dst
//   [2(E+NN), 2(E+NN)+E) : edge_attr copy
//   [2(E+NN)+E, 3(E+NN)) : new_attr (3.0 if shortcut else -1.0)

#define N_NODES 1024
#define NW 32
#define FULLMASK 0xFFFFFFFFu

static __device__ uint32_t g_adj[N_NODES * NW];
static __device__ uint32_t g_radj[N_NODES * NW];
static __device__ uint32_t g_F[NW];
static __device__ uint32_t g_B[NW];
static __device__ int g_pivot;
static __device__ int g_i64flag;

// ---------------------------------------------------------------------------
// K1: zero scratch, detect dtype. 128 blocks x 256 threads.
__global__ void init_kernel(const int* __restrict__ ei32) {
    int t = blockIdx.x * blockDim.x + threadIdx.x;   // 0..32767
    g_adj[t] = 0u;
    g_radj[t] = 0u;
    if (t == 0) {
        g_pivot = -1;
        // int64 little-endian with node ids < 1024 => every odd word is 0.
        int allzero = 1;
        for (int k = 0; k < 64; k++)
            if (ei32[2 * k + 1] != 0) { allzero = 0; break; }
        g_i64flag = allzero;
    }
}

// ---------------------------------------------------------------------------
// K2: scatter adj/radj + pivot + copy originals. One edge per thread.
__global__ void build_kernel(const int* __restrict__ ei32,
                             const float* __restrict__ attr,
                             float* __restrict__ out, int E) {
    __shared__ int sPivMax;
    const int NN = N_NODES * N_NODES;
    if (threadIdx.x == 0) sPivMax = -1;
    __syncthreads();

    int e = blockIdx.x * blockDim.x + threadIdx.x;
    int lane = threadIdx.x & 31;
    bool v = (e < E);
    int src = 0, dst = 0; float a = 1.0f;
    if (v) {
        if (g_i64flag) { src = ei32[2 * e]; dst = ei32[2 * (E + e)]; }
        else           { src = ei32[e];     dst = ei32[E + e]; }
        a = attr[e];
        out[e] = (float)src;
        out[(E + NN) + e] = (float)dst;
        out[2 * (E + NN) + e] = a;
    }
    bool body = v && (a == 0.0f);
    if (body) {
        atomicOr(&g_adj[src * NW + (dst >> 5)], 1u << (dst & 31));
        atomicOr(&g_radj[dst * NW + (src >> 5)], 1u << (src & 31));
    }
    int m = __reduce_max_sync(FULLMASK, body ? dst : -1);
    if (lane == 0 && m >= 0) atomicMax(&sPivMax, m);
    __syncthreads();
    if (threadIdx.x == 0 && sPivMax >= 0) atomicMax(&g_pivot, sPivMax);
}

// ---------------------------------------------------------------------------
// K3: single-source BFS to fixpoint. block 0: forward -> g_F;
//     block 1: backward -> g_B. 32 warps, 1 frontier word per warp.
__global__ void __launch_bounds__(1024) bfs_kernel() {
    __shared__ uint32_t sR[NW];
    const int lane = threadIdx.x & 31;
    const int wid  = threadIdx.x >> 5;               // 0..31

    const uint32_t* Adj = (blockIdx.x == 0) ? g_adj : g_radj;
    const int p = g_pivot;
    if (lane == 0) sR[wid] = (p >= 0) ? Adj[p * NW + wid] : 0u;
    __syncthreads();

    if (p >= 0) {
        uint32_t expanded = 0;                       // own word, in register
        #pragma unroll 1
        for (int level = 0; level < N_NODES + 1; level++) {
            uint32_t cur = sR[wid];                  // post-sync, merged
            uint32_t fr = cur & ~expanded;           // warp-uniform
            expanded = cur;
            if (!__syncthreads_or(fr != 0u)) break;

            uint32_t accum = 0;                      // lane l = word l
            const uint32_t* pk = &Adj[(wid << 10) + lane];
            uint32_t bits = fr;
            while (bits) {
                int j0 = __ffs(bits) - 1; bits &= bits - 1;
                int j1 = j0, j2 = j0, j3 = j0;
                int j4 = j0, j5 = j0, j6 = j0, j7 = j0;
                if (bits) { j1 = __ffs(bits) - 1; bits &= bits - 1; }
                if (bits) { j2 = __ffs(bits) - 1; bits &= bits - 1; }
                if (bits) { j3 = __ffs(bits) - 1; bits &= bits - 1; }
                if (bits) { j4 = __ffs(bits) - 1; bits &= bits - 1; }
                if (bits) { j5 = __ffs(bits) - 1; bits &= bits - 1; }
                if (bits) { j6 = __ffs(bits) - 1; bits &= bits - 1; }
                if (bits) { j7 = __ffs(bits) - 1; bits &= bits - 1; }
                uint32_t v0 = pk[j0 << 5];
                uint32_t v1 = pk[j1 << 5];
                uint32_t v2 = pk[j2 << 5];
                uint32_t v3 = pk[j3 << 5];
                uint32_t v4 = pk[j4 << 5];
                uint32_t v5 = pk[j5 << 5];
                uint32_t v6 = pk[j6 << 5];
                uint32_t v7 = pk[j7 << 5];
                accum |= (v0 | v1) | (v2 | v3) | (v4 | v5) | (v6 | v7);
            }
            if (accum) atomicOr(&sR[lane], accum);
            __syncthreads();
        }
    }
    if (threadIdx.x < NW) {
        if (blockIdx.x == 0) g_F[threadIdx.x] = sR[threadIdx.x];
        else                 g_B[threadIdx.x] = sR[threadIdx.x];
    }
}

// ---------------------------------------------------------------------------
// K4: per-warp closed-form closure + coalesced full-row emit.
// 128 blocks x 256 threads = 1024 warps, warp == row (8 warps/SM).
__global__ void __launch_bounds__(256)
closure_emit_kernel(float* __restrict__ out, int E) {
    __shared__ uint32_t sF[NW], sB[NW];
    __shared__ int sPiv;

    const int tid  = blockIdx.x * 256 + threadIdx.x;
    const int lane = threadIdx.x & 31;
    const int row  = tid >> 5;                       // 0..1023
    const int NN   = N_NODES * N_NODES;

    if (threadIdx.x < NW)            sF[threadIdx.x] = g_F[threadIdx.x];
    else if (threadIdx.x < 2 * NW)   sB[threadIdx.x - NW] = g_B[threadIdx.x - NW];
    else if (threadIdx.x == 2 * NW)  sPiv = g_pivot;
    __syncthreads();

    const uint32_t Fl  = sF[lane];                   // conflict-free broadcast
    const uint32_t Bl  = sB[lane];
    const uint32_t FBl = Fl & Bl;
    const int p = sPiv;
    const uint32_t pbit = (p >= 0 && lane == (p >> 5)) ? (1u << (p & 31)) : 0u;

    const uint32_t adjrow = g_adj[(row << 5) + lane];
    const int inB = (__shfl_sync(FULLMASK, Bl, row >> 5) >> (row & 31)) & 1;

    uint32_t acc = adjrow;
    bool haveF = false;
    if (inB) { acc |= Fl | pbit; haveF = true; }     // closure(row) >= F u {p}
    uint32_t expanded = 0;

    #pragma unroll 1
    for (int round = 0; round < N_NODES; round++) {
        uint32_t delta = acc & ~expanded;
        if (!__any_sync(FULLMASK, delta != 0u)) break;
        expanded = acc;
        uint32_t add = 0;

        bool hitB = __any_sync(FULLMASK, (delta & Bl) != 0u);
        bool willF = haveF || hitB;
        if (hitB) add |= Fl | pbit;

        uint32_t loadbits = delta & ~FBl;            // F&B: closure=F, no load
        if (willF) loadbits &= ~Fl;                  // F absorbed once in acc

        uint32_t wordmask = __ballot_sync(FULLMASK, loadbits != 0u);
        while (wordmask) {
            int l = __ffs(wordmask) - 1; wordmask &= wordmask - 1;
            uint32_t bits = __shfl_sync(FULLMASK, loadbits, l);
            const uint32_t* pk = &g_adj[(l << 10) + lane];
            while (bits) {
                int j0 = __ffs(bits) - 1; bits &= bits - 1;
                int j1 = j0, j2 = j0, j3 = j0;
                if (bits) { j1 = __ffs(bits) - 1; bits &= bits - 1; }
                if (bits) { j2 = __ffs(bits) - 1; bits &= bits - 1; }
                if (bits) { j3 = __ffs(bits) - 1; bits &= bits - 1; }
                add |= pk[j0 << 5] | pk[j1 << 5] | pk[j2 << 5] | pk[j3 << 5];
            }
        }

        uint32_t na = acc | add;
        haveF = willF;
        if (__all_sync(FULLMASK, na == acc)) break;
        acc = na;
    }

    // sc for lane's word (row*32+lane); row output span is contiguous.
    uint32_t sc = acc & ~adjrow;
    const float fi = (float)row;
    float* so = out + E + (row << 10);                    // new_src row
    float* dd = out + (E + NN) + E + (row << 10);         // new_dst row
    float* ao = out + 2 * (E + NN) + E + (row << 10);     // new_attr row

    if ((E & 3) == 0) {
        // Coalesced: 8 iterations x 3 float4 stores; lane l covers floats
        // f = it*128 + l*4 + {0..3}; word = it*4 + (l>>3); bit = (l&7)*4+q.
        #pragma unroll
        for (int it = 0; it < 8; it++) {
            int w = (it << 2) + (lane >> 3);
            uint32_t nib = (__shfl_sync(FULLMASK, sc, w) >> ((lane & 7) << 2)) & 0xFu;
            int f = (it << 7) + (lane << 2);
            bool b0 = nib & 1u, b1 = (nib >> 1) & 1u;
            bool b2 = (nib >> 2) & 1u, b3 = (nib >> 3) & 1u;
            float4 s4 = make_float4(b0 ? fi : 0.f, b1 ? fi : 0.f,
                                    b2 ? fi : 0.f, b3 ? fi : 0.f);
            float4 d4 = make_float4(b0 ? (float)(f + 0) : 0.f,
                                    b1 ? (float)(f + 1) : 0.f,
                                    b2 ? (float)(f + 2) : 0.f,
                                    b3 ? (float)(f + 3) : 0.f);
            float4 a4 = make_float4(b0 ? 3.f : -1.f, b1 ? 3.f : -1.f,
                                    b2 ? 3.f : -1.f, b3 ? 3.f : -1.f);
            *(float4*)(so + f) = s4;
            *(float4*)(dd + f) = d4;
            *(float4*)(ao + f) = a4;
        }
    } else {
        // Scalar fallback (unaligned E). Still coalesced per instruction.
        #pragma unroll 1
        for (int it = 0; it < 32; it++) {
            int f = (it << 5) + lane;                // float index in row
            uint32_t scw = __shfl_sync(FULLMASK, sc, f >> 5);
            bool b = (scw >> (f & 31)) & 1u;
            so[f] = b ? fi : 0.f;
            dd[f] = b ? (float)f : 0.f;
            ao[f] = b ? 3.f : -1.f;
        }
    }
}

// ---------------------------------------------------------------------------
extern "C" void kernel_launch(void* const* d_in, const int* in_sizes, int n_in,
                              void* d_out, int out_size) {
    const int* ei = (const int*)d_in[0];
    const float* attr = (const float*)d_in[1];
    float* out = (float*)d_out;
    int E = in_sizes[1];

    init_kernel<<<128, 256>>>(ei);
    build_kernel<<<(E + 255) / 256, 256>>>(ei, attr, out, E);
    bfs_kernel<<<2, 1024>>>();
    closure_emit_kernel<<<128, 256>>>(out, E);
}